// round 3
// baseline (speedup 1.0000x reference)
#include <cuda_runtime.h>
#include <cmath>

#define NB   128      // batch
#define LSEQ 160      // sequence length
#define EMB  512      // embedding dim
#define HE   512      // encoder hidden per direction
#define HD   1024     // decoder hidden (= 2*HE)
#define TT   128      // tag count
#define NGATE 4096    // 2 dirs * 4*HE (also = 4*HD for decoder)
#define GRID 128      // persistent-kernel grid (all co-resident on 148 SMs)

// ---------------- scratch (static device globals; no runtime allocation) ----------------
static __device__ float g_GBUF[(size_t)LSEQ * NB * NGATE];   // input-proj gates (reused)
static __device__ float g_H1 [(size_t)LSEQ * NB * (2 * HE)]; // layer0 bidir output
static __device__ float g_ENC[(size_t)LSEQ * NB * (2 * HE)]; // layer1 bidir output
static __device__ float g_h_enc[2 * NB * HE];
static __device__ float g_c_enc[2 * NB * HE];
static __device__ float g_Gcur[NB * NGATE];
static __device__ float g_hdec[NB * HD];
static __device__ float g_cdec[NB * HD];
static __device__ int   g_previdx[NB];
static __device__ float g_loss;
static __device__ unsigned g_arrive;   // grid-barrier counter (phase bit = bit 31)

__device__ __forceinline__ float sigm(float x) { return 1.0f / (1.0f + expf(-x)); }

// CG-style grid barrier: release-add by one thread per CTA, acquire-spin, bar.sync chain.
// Valid because all GRID CTAs are co-resident (grid <= #SMs, 1 CTA/SM fits).
__device__ __forceinline__ void sync_grid()
{
    __syncthreads();
    if (threadIdx.x == 0) {
        unsigned add = (blockIdx.x == 0) ? (0x80000000u - (GRID - 1u)) : 1u;
        unsigned old, cur;
        asm volatile("atom.add.release.gpu.u32 %0, [%1], %2;"
                     : "=r"(old) : "l"(&g_arrive), "r"(add) : "memory");
        do {
            asm volatile("ld.acquire.gpu.u32 %0, [%1];"
                         : "=r"(cur) : "l"(&g_arrive) : "memory");
        } while (((old ^ cur) & 0x80000000u) == 0);
    }
    __syncthreads();
}

// ---------------- big input-projection GEMM (128x128 tile, 8x8 per thread) ----------------
// C[m][j] = sum_k A[m][k] * W[j][k] + bias[j]   (M = LSEQ*NB = 20480, N = 4096)
// GATHER=1: A[m][k] = embed[input_ids[(m%NB)*LSEQ + m/NB]][k], K=512
// GATHER=0: A = g_H1, K=1024
template <int GATHER, int K>
__global__ __launch_bounds__(256) void inproj_gemm(
    const float* __restrict__ W, const float* __restrict__ bias,
    const float* __restrict__ embed, const int* __restrict__ ids)
{
    __shared__ __align__(16) float As[16][132];
    __shared__ __align__(16) float Bs[16][132];
    __shared__ int rowoff[128];
    int tid = threadIdx.x;
    int row0 = blockIdx.y * 128;
    int col0 = blockIdx.x * 128;
    if (GATHER) {
        if (tid < 128) {
            int m = row0 + tid;
            rowoff[tid] = ids[(m & (NB - 1)) * LSEQ + (m >> 7)] * EMB;
        }
        __syncthreads();
    }
    int tx = tid & 15, ty = tid >> 4;
    float acc[8][8];
#pragma unroll
    for (int i = 0; i < 8; i++)
#pragma unroll
        for (int j = 0; j < 8; j++) acc[i][j] = 0.f;

    for (int k0 = 0; k0 < K; k0 += 16) {
#pragma unroll
        for (int p = 0; p < 8; p++) {
            int idx = tid + p * 256;
            int kk = idx & 15, m = idx >> 4;
            float v;
            if (GATHER) v = embed[rowoff[m] + k0 + kk];
            else        v = g_H1[(size_t)(row0 + m) * K + k0 + kk];
            As[kk][m] = v;
        }
#pragma unroll
        for (int p = 0; p < 8; p++) {
            int idx = tid + p * 256;
            int kk = idx & 15, j = idx >> 4;
            Bs[kk][j] = W[(size_t)(col0 + j) * K + k0 + kk];
        }
        __syncthreads();
#pragma unroll
        for (int kk = 0; kk < 16; kk++) {
            float4 a0 = *(const float4*)&As[kk][ty * 8];
            float4 a1 = *(const float4*)&As[kk][ty * 8 + 4];
            float4 b0 = *(const float4*)&Bs[kk][tx * 8];
            float4 b1 = *(const float4*)&Bs[kk][tx * 8 + 4];
            float a[8] = {a0.x, a0.y, a0.z, a0.w, a1.x, a1.y, a1.z, a1.w};
            float b[8] = {b0.x, b0.y, b0.z, b0.w, b1.x, b1.y, b1.z, b1.w};
#pragma unroll
            for (int i = 0; i < 8; i++)
#pragma unroll
                for (int j = 0; j < 8; j++) acc[i][j] += a[i] * b[j];
        }
        __syncthreads();
    }
#pragma unroll
    for (int i = 0; i < 8; i++) {
        int m = row0 + ty * 8 + i;
        float* dst = &g_GBUF[(size_t)m * NGATE + col0 + tx * 8];
#pragma unroll
        for (int q = 0; q < 2; q++) {
            int jg = col0 + tx * 8 + q * 4;
            float4 v;
            v.x = acc[i][q * 4 + 0] + bias[jg + 0];
            v.y = acc[i][q * 4 + 1] + bias[jg + 1];
            v.z = acc[i][q * 4 + 2] + bias[jg + 2];
            v.w = acc[i][q * 4 + 3] + bias[jg + 3];
            *(float4*)(dst + q * 4) = v;
        }
    }
}

// ---------------- persistent encoder layer: 160 steps in one launch ----------------
__global__ __launch_bounds__(256) void enc_layer_persistent(
    const float* __restrict__ whh, int layer)
{
    int tid = threadIdx.x, bid = blockIdx.x;
    // init h, c
#pragma unroll
    for (int p = 0; p < 4; p++) {
        int idx = (bid * 4 + p) * 256 + tid;
        g_h_enc[idx] = 0.f;
        g_c_enc[idx] = 0.f;
    }
    sync_grid();

    __shared__ float As[16][129];
    __shared__ float Bs[16][33];
    int tx = tid & 15, ty = tid >> 4;
    int col0 = bid * 32;                 // 128 CTAs cover 4096 gate cols
    int dir = col0 >> 11;
    const float* W = whh + (size_t)col0 * HE;   // (2,2048,512) -> flat row col0
    const float* A = g_h_enc + dir * NB * HE;
    float* H = layer ? g_ENC : g_H1;

    for (int t = 0; t < LSEQ; t++) {
        int time = dir ? (LSEQ - 1 - t) : t;
        // ---- recurrent GEMM phase ----
        float acc[8][2];
#pragma unroll
        for (int i = 0; i < 8; i++) { acc[i][0] = 0.f; acc[i][1] = 0.f; }
        for (int k0 = 0; k0 < HE; k0 += 16) {
#pragma unroll
            for (int p = 0; p < 8; p++) {
                int idx = tid + p * 256;
                int kk = idx & 15, m = idx >> 4;
                As[kk][m] = A[m * HE + k0 + kk];
            }
#pragma unroll
            for (int p = 0; p < 2; p++) {
                int idx = tid + p * 256;
                int kk = idx & 15, j = idx >> 4;
                Bs[kk][j] = W[j * HE + k0 + kk];
            }
            __syncthreads();
#pragma unroll
            for (int kk = 0; kk < 16; kk++) {
                float b0 = Bs[kk][tx * 2], b1 = Bs[kk][tx * 2 + 1];
#pragma unroll
                for (int i = 0; i < 8; i++) {
                    float av = As[kk][ty * 8 + i];
                    acc[i][0] += av * b0;
                    acc[i][1] += av * b1;
                }
            }
            __syncthreads();
        }
        {
            const float* Gin = g_GBUF + (size_t)time * NB * NGATE;
#pragma unroll
            for (int i = 0; i < 8; i++) {
                int m = ty * 8 + i;
#pragma unroll
                for (int j = 0; j < 2; j++) {
                    int jg = col0 + tx * 2 + j;
                    g_Gcur[m * NGATE + jg] = acc[i][j] + Gin[(size_t)m * NGATE + jg];
                }
            }
        }
        sync_grid();
        // ---- pointwise LSTM phase ----
#pragma unroll
        for (int p = 0; p < 4; p++) {
            int idx = (bid * 4 + p) * 256 + tid;       // 0 .. 2*NB*HE-1
            int j  = idx & (HE - 1);
            int n  = (idx >> 9) & (NB - 1);
            int d2 = idx >> 16;
            const float* G = g_Gcur + n * NGATE + d2 * 2048;
            float gi = G[j], gf = G[512 + j], gg = G[1024 + j], go = G[1536 + j];
            float cc = g_c_enc[idx];
            cc = sigm(gf) * cc + sigm(gi) * tanhf(gg);
            float hh = sigm(go) * tanhf(cc);
            g_c_enc[idx] = cc;
            g_h_enc[idx] = hh;
            int tm = d2 ? (LSEQ - 1 - t) : t;
            H[((size_t)tm * NB + n) * HD + d2 * HE + j] = hh;
        }
        sync_grid();
    }
}

// ---------------- persistent decoder: 160 steps in one launch ----------------
__global__ __launch_bounds__(256) void dec_persistent(
    const float* __restrict__ whh, const float* __restrict__ bias,
    const float* __restrict__ wih,
    const float* __restrict__ out_w, const float* __restrict__ out_b,
    const int* __restrict__ tag_ids, float* __restrict__ prob_out)
{
    int tid = threadIdx.x, bid = blockIdx.x;
    // init
#pragma unroll
    for (int p = 0; p < 4; p++) {
        int idx = (bid * 4 + p) * 256 + tid;           // 0 .. NB*HD-1
        int n = idx >> 10, j = idx & (HD - 1);
        g_hdec[idx] = 0.f;
        g_cdec[idx] = g_ENC[(size_t)n * HD + HE + (j & (HE - 1))];   // cell0
    }
    if (bid == 0 && tid < NB) g_previdx[tid] = -1;
    if (bid == 0 && tid == 0) g_loss = 0.f;
    sync_grid();

    __shared__ float As[16][129];
    __shared__ float Bs[16][33];
    __shared__ float sh[HD];
    __shared__ float red[256];
    __shared__ float logitsS[TT];
    __shared__ float sLogZ;
    __shared__ int sArg;
    int tx = tid & 15, ty = tid >> 4;
    int col0 = bid * 32;
    const float* W = whh + (size_t)col0 * HD;

    for (int t = 0; t < LSEQ; t++) {
        const float* Enc = g_ENC + (size_t)t * NB * HD;
        // ---- gate GEMM phase: G = (h + enc_t) @ whh^T + b + wih[:,prev] ----
        float acc[8][2];
#pragma unroll
        for (int i = 0; i < 8; i++) { acc[i][0] = 0.f; acc[i][1] = 0.f; }
        for (int k0 = 0; k0 < HD; k0 += 16) {
#pragma unroll
            for (int p = 0; p < 8; p++) {
                int idx = tid + p * 256;
                int kk = idx & 15, m = idx >> 4;
                As[kk][m] = g_hdec[m * HD + k0 + kk] + Enc[m * HD + k0 + kk];
            }
#pragma unroll
            for (int p = 0; p < 2; p++) {
                int idx = tid + p * 256;
                int kk = idx & 15, j = idx >> 4;
                Bs[kk][j] = W[j * HD + k0 + kk];
            }
            __syncthreads();
#pragma unroll
            for (int kk = 0; kk < 16; kk++) {
                float b0 = Bs[kk][tx * 2], b1 = Bs[kk][tx * 2 + 1];
#pragma unroll
                for (int i = 0; i < 8; i++) {
                    float av = As[kk][ty * 8 + i];
                    acc[i][0] += av * b0;
                    acc[i][1] += av * b1;
                }
            }
            __syncthreads();
        }
#pragma unroll
        for (int i = 0; i < 8; i++) {
            int m = ty * 8 + i;
            int pi = g_previdx[m];
#pragma unroll
            for (int j = 0; j < 2; j++) {
                int jg = col0 + tx * 2 + j;
                float v = acc[i][j] + bias[jg];
                if (pi >= 0) v += wih[jg * TT + pi];   // one-hot input == column gather
                g_Gcur[m * NGATE + jg] = v;
            }
        }
        sync_grid();
        // ---- pointwise + logits + softmax phase: CTA bid handles batch row bid ----
        {
            int n = bid;
            const float* G = g_Gcur + n * NGATE;
#pragma unroll
            for (int p = 0; p < 4; p++) {
                int j = tid + p * 256;
                float gi = G[j], gf = G[HD + j], gg = G[2 * HD + j], go = G[3 * HD + j];
                float cc = g_cdec[n * HD + j];
                cc = sigm(gf) * cc + sigm(gi) * tanhf(gg);
                float hh = sigm(go) * tanhf(cc);
                g_cdec[n * HD + j] = cc;
                g_hdec[n * HD + j] = hh;
                sh[j] = hh;
            }
            __syncthreads();
            {
                int lj = tid & (TT - 1), half = tid >> 7;
                const float* wr = out_w + (size_t)lj * HD + half * 512;
                const float* hr = sh + half * 512;
                float s = 0.f;
#pragma unroll 8
                for (int k = 0; k < 512; k++) s += hr[k] * wr[k];
                red[tid] = s;
            }
            __syncthreads();
            if (tid < TT) logitsS[tid] = red[tid] + red[tid + TT] + out_b[tid];
            __syncthreads();
            if (tid < 32) {
                float bv = -1e30f; int bi = 0;
#pragma unroll
                for (int p = 0; p < 4; p++) {
                    int k = tid + p * 32;
                    float v = logitsS[k];
                    if (v > bv) { bv = v; bi = k; }
                }
#pragma unroll
                for (int off = 16; off; off >>= 1) {
                    float ov = __shfl_down_sync(0xffffffffu, bv, off);
                    int   oi = __shfl_down_sync(0xffffffffu, bi, off);
                    if (ov > bv || (ov == bv && oi < bi)) { bv = ov; bi = oi; }
                }
                bv = __shfl_sync(0xffffffffu, bv, 0);
                bi = __shfl_sync(0xffffffffu, bi, 0);
                float s = 0.f;
#pragma unroll
                for (int p = 0; p < 4; p++) s += expf(logitsS[tid + p * 32] - bv);
#pragma unroll
                for (int off = 16; off; off >>= 1) s += __shfl_down_sync(0xffffffffu, s, off);
                if (tid == 0) { sLogZ = bv + logf(s); sArg = bi; }
            }
            __syncthreads();
            if (tid < TT)
                prob_out[(size_t)n * (LSEQ * TT) + t * TT + tid] = expf(logitsS[tid] - sLogZ);
            if (tid == 0) {
                g_previdx[n] = sArg;
                int tag = tag_ids[n * LSEQ + t];
                atomicAdd(&g_loss, -(logitsS[tag] - sLogZ) * (1.0f / NB));
            }
        }
        sync_grid();
    }
    if (bid == 0 && tid == 0) prob_out[(size_t)NB * LSEQ * TT] = g_loss;
}

// ---------------- launch: 5 graph nodes total ----------------
extern "C" void kernel_launch(void* const* d_in, const int* in_sizes, int n_in,
                              void* d_out, int out_size)
{
    const int*   input_ids = (const int*)d_in[0];
    const int*   tag_ids   = (const int*)d_in[1];
    const float* embed     = (const float*)d_in[2];
    const float* e0_wih    = (const float*)d_in[3];
    const float* e0_whh    = (const float*)d_in[4];
    const float* e0_b      = (const float*)d_in[5];
    const float* e1_wih    = (const float*)d_in[6];
    const float* e1_whh    = (const float*)d_in[7];
    const float* e1_b      = (const float*)d_in[8];
    const float* dec_wih   = (const float*)d_in[9];
    const float* dec_whh   = (const float*)d_in[10];
    const float* dec_b     = (const float*)d_in[11];
    const float* out_w     = (const float*)d_in[12];
    const float* out_b     = (const float*)d_in[13];
    float* out = (float*)d_out;
    (void)in_sizes; (void)n_in; (void)out_size;

    dim3 ggrid(NGATE / 128, (LSEQ * NB) / 128);   // 32 x 160

    inproj_gemm<1, EMB><<<ggrid, 256>>>(e0_wih, e0_b, embed, input_ids);
    enc_layer_persistent<<<GRID, 256>>>(e0_whh, 0);
    inproj_gemm<0, HD><<<ggrid, 256>>>(e1_wih, e1_b, embed, input_ids);
    enc_layer_persistent<<<GRID, 256>>>(e1_whh, 1);
    dec_persistent<<<GRID, 256>>>(dec_whh, dec_b, dec_wih, out_w, out_b, tag_ids, out);
}

// round 7
// speedup vs baseline: 1.2855x; 1.2855x over previous
#include <cuda_runtime.h>
#include <cmath>

#define NB   128
#define LSEQ 160
#define EMB  512
#define HE   512
#define HD   1024
#define TT   128
#define NGATE 4096
#define GRID 128

// ---------------- scratch ----------------
static __device__ float g_GBUF[(size_t)LSEQ * NB * NGATE];   // input-proj gates (PERMUTED cols)
static __device__ float g_H1 [(size_t)LSEQ * NB * (2 * HE)];
static __device__ float g_ENC[(size_t)LSEQ * NB * (2 * HE)];
static __device__ float g_henc[2][2 * NB * HE];              // encoder h, ping-pong
static __device__ float g_hraw[NB * HD];                     // decoder raw h_t (logits input)
static __device__ float g_hsum[2][NB * HD];                  // decoder h_{t-1}+enc_t, ping-pong
static __device__ int   g_previdx[NB];
static __device__ float g_loss;
static __device__ unsigned g_arrive;

__device__ __forceinline__ float sigm(float x) { return 1.0f / (1.0f + expf(-x)); }

// tf32 helpers: exact-ish fp32 GEMM via 3-term split
__device__ __forceinline__ unsigned tf32_of(float x) {
    unsigned u; asm("cvt.rna.tf32.f32 %0, %1;" : "=r"(u) : "f"(x)); return u;
}
__device__ __forceinline__ void tf32_split(float x, unsigned& hi, unsigned& lo) {
    hi = tf32_of(x);
    lo = tf32_of(x - __uint_as_float(hi));
}
__device__ __forceinline__ void mma8(float* c, unsigned a0, unsigned a1, unsigned a2, unsigned a3,
                                     unsigned b0, unsigned b1) {
    asm volatile("mma.sync.aligned.m16n8k8.row.col.f32.tf32.tf32.f32 "
                 "{%0,%1,%2,%3}, {%4,%5,%6,%7}, {%8,%9}, {%0,%1,%2,%3};"
                 : "+f"(c[0]), "+f"(c[1]), "+f"(c[2]), "+f"(c[3])
                 : "r"(a0), "r"(a1), "r"(a2), "r"(a3), "r"(b0), "r"(b1));
}

// grid barrier with backoff (all GRID CTAs co-resident)
__device__ __forceinline__ void sync_grid()
{
    __syncthreads();
    if (threadIdx.x == 0) {
        unsigned add = (blockIdx.x == 0) ? (0x80000000u - (GRID - 1u)) : 1u;
        unsigned old, cur;
        asm volatile("atom.add.release.gpu.u32 %0, [%1], %2;"
                     : "=r"(old) : "l"(&g_arrive), "r"(add) : "memory");
        int spins = 0;
        for (;;) {
            asm volatile("ld.acquire.gpu.u32 %0, [%1];"
                         : "=r"(cur) : "l"(&g_arrive) : "memory");
            if ((old ^ cur) & 0x80000000u) break;
            if (++spins > 16) __nanosleep(64);
        }
    }
    __syncthreads();
}

// permuted-col map (encoder, per 2048-col dir block):
// p = jblk*32 + gate*8 + jj  <->  natural = gate*512 + jblk*8 + jj

// ---------------- input-projection GEMM (tf32x3 mma), writes PERMUTED gate cols ----------------
template <int GATHER, int K>
__global__ __launch_bounds__(256) void inproj_gemm(
    const float* __restrict__ W, const float* __restrict__ bias,
    const float* __restrict__ embed, const int* __restrict__ ids)
{
    __shared__ float sA[128 * 20];
    __shared__ float sB[128 * 20];
    __shared__ int   rowoff[128];
    __shared__ int   natrow[128];
    __shared__ float sBias[128];
    int tid = threadIdx.x;
    int row0 = blockIdx.y * 128;
    int col0 = blockIdx.x * 128;
    if (tid < 128) {
        int p = col0 + tid;
        int dir = p >> 11;
        int q = p & 2047;
        int nat = dir * 2048 + ((q >> 3) & 3) * 512 + (q >> 5) * 8 + (q & 7);
        natrow[tid] = nat;
        sBias[tid] = bias[nat];
        if (GATHER) {
            int m = row0 + tid;
            rowoff[tid] = ids[(m & (NB - 1)) * LSEQ + (m >> 7)] * EMB;
        }
    }
    __syncthreads();
    int lane = tid & 31, w = tid >> 5;
    int wm = w >> 2, wn = w & 3;
    float acc[4][4][4];
#pragma unroll
    for (int a = 0; a < 4; a++)
#pragma unroll
        for (int b = 0; b < 4; b++)
#pragma unroll
            for (int c = 0; c < 4; c++) acc[a][b][c] = 0.f;

    for (int k0 = 0; k0 < K; k0 += 16) {
#pragma unroll
        for (int p = 0; p < 8; p++) {
            int idx = tid + p * 256;
            int r = idx >> 4, c = idx & 15;
            float v;
            if (GATHER) v = embed[rowoff[r] + k0 + c];
            else        v = g_H1[(size_t)(row0 + r) * K + k0 + c];
            sA[r * 20 + c] = v;
            sB[r * 20 + c] = W[(size_t)natrow[r] * K + k0 + c];
        }
        __syncthreads();
#pragma unroll
        for (int kk = 0; kk < 16; kk += 8) {
            unsigned ah[4][4], al[4][4];
#pragma unroll
            for (int mf = 0; mf < 4; mf++) {
                int ar = wm * 64 + mf * 16 + (lane >> 2);
                int ac = kk + (lane & 3);
                tf32_split(sA[ar * 20 + ac],           ah[mf][0], al[mf][0]);
                tf32_split(sA[(ar + 8) * 20 + ac],     ah[mf][1], al[mf][1]);
                tf32_split(sA[ar * 20 + ac + 4],       ah[mf][2], al[mf][2]);
                tf32_split(sA[(ar + 8) * 20 + ac + 4], ah[mf][3], al[mf][3]);
            }
#pragma unroll
            for (int nf = 0; nf < 4; nf++) {
                int br = wn * 32 + nf * 8 + (lane >> 2);
                int bc = kk + (lane & 3);
                unsigned bh0, bl0, bh1, bl1;
                tf32_split(sB[br * 20 + bc],     bh0, bl0);
                tf32_split(sB[br * 20 + bc + 4], bh1, bl1);
#pragma unroll
                for (int mf = 0; mf < 4; mf++) {
                    mma8(acc[mf][nf], al[mf][0], al[mf][1], al[mf][2], al[mf][3], bh0, bh1);
                    mma8(acc[mf][nf], ah[mf][0], ah[mf][1], ah[mf][2], ah[mf][3], bl0, bl1);
                    mma8(acc[mf][nf], ah[mf][0], ah[mf][1], ah[mf][2], ah[mf][3], bh0, bh1);
                }
            }
        }
        __syncthreads();
    }
#pragma unroll
    for (int mf = 0; mf < 4; mf++) {
        int r = row0 + wm * 64 + mf * 16 + (lane >> 2);
#pragma unroll
        for (int nf = 0; nf < 4; nf++) {
            int jl = wn * 32 + nf * 8 + (lane & 3) * 2;
            int jg = col0 + jl;
            float2 v0 = make_float2(acc[mf][nf][0] + sBias[jl], acc[mf][nf][1] + sBias[jl + 1]);
            float2 v1 = make_float2(acc[mf][nf][2] + sBias[jl], acc[mf][nf][3] + sBias[jl + 1]);
            *(float2*)&g_GBUF[(size_t)r * NGATE + jg] = v0;
            *(float2*)&g_GBUF[(size_t)(r + 8) * NGATE + jg] = v1;
        }
    }
}

// ---------------- persistent encoder layer ----------------
__global__ __launch_bounds__(256) void enc_layer_persistent(
    const float* __restrict__ whh, int layer)
{
    int tid = threadIdx.x, bid = blockIdx.x;
    int lane = tid & 31, w = tid >> 5;
#pragma unroll
    for (int p = 0; p < 4; p++) {
        int idx = (bid * 4 + p) * 256 + tid;
        g_henc[0][idx] = 0.f;
    }
    sync_grid();

    __shared__ float sA[128 * 36];
    __shared__ float sB[32 * 36];
    int dir = bid >> 6;
    int jblk = bid & 63;
    int p_base = bid * 32;
    float* Hout = layer ? g_ENC : g_H1;

    // register cell state: 4 cells per thread (rows r0, r0+8; cols jj2, jj2+1)
    float creg[4] = {0.f, 0.f, 0.f, 0.f};
    int r0 = (w << 4) + (lane >> 2);
    int jj2 = (lane & 3) * 2;

    for (int t = 0; t < LSEQ; t++) {
        int time = dir ? (LSEQ - 1 - t) : t;
        const float* A = g_henc[t & 1] + dir * NB * HE;
        float* Awr = g_henc[(t + 1) & 1] + dir * NB * HE;
        float acc[4][4];
#pragma unroll
        for (int a = 0; a < 4; a++)
#pragma unroll
            for (int c = 0; c < 4; c++) acc[a][c] = 0.f;

        for (int k0 = 0; k0 < HE; k0 += 32) {
#pragma unroll
            for (int p = 0; p < 16; p++) {
                int idx = tid + p * 256;
                int r = idx >> 5, c = idx & 31;
                sA[r * 36 + c] = A[r * HE + k0 + c];
            }
#pragma unroll
            for (int p = 0; p < 4; p++) {
                int idx = tid + p * 256;
                int r = idx >> 5, c = idx & 31;
                int nat = dir * 2048 + (r >> 3) * 512 + jblk * 8 + (r & 7);
                sB[r * 36 + c] = whh[(size_t)nat * HE + k0 + c];
            }
            __syncthreads();
#pragma unroll
            for (int kk = 0; kk < 32; kk += 8) {
                int ar = r0;
                int ac = kk + (lane & 3);
                unsigned ah[4], al[4];
                tf32_split(sA[ar * 36 + ac],           ah[0], al[0]);
                tf32_split(sA[(ar + 8) * 36 + ac],     ah[1], al[1]);
                tf32_split(sA[ar * 36 + ac + 4],       ah[2], al[2]);
                tf32_split(sA[(ar + 8) * 36 + ac + 4], ah[3], al[3]);
#pragma unroll
                for (int nf = 0; nf < 4; nf++) {
                    int br = nf * 8 + (lane >> 2);
                    int bc = kk + (lane & 3);
                    unsigned bh0, bl0, bh1, bl1;
                    tf32_split(sB[br * 36 + bc],     bh0, bl0);
                    tf32_split(sB[br * 36 + bc + 4], bh1, bl1);
                    mma8(acc[nf], al[0], al[1], al[2], al[3], bh0, bh1);
                    mma8(acc[nf], ah[0], ah[1], ah[2], ah[3], bl0, bl1);
                    mma8(acc[nf], ah[0], ah[1], ah[2], ah[3], bh0, bh1);
                }
            }
            __syncthreads();
        }
        // in-register pointwise; writes go to the OTHER h buffer (no cross-CTA race)
        {
            const float* Gin = g_GBUF + ((size_t)time * NB) * NGATE + p_base;
#pragma unroll
            for (int cell = 0; cell < 4; cell++) {
                int rr = r0 + (cell >> 1) * 8;
                int jloc = jj2 + (cell & 1);
                const float* Gr = Gin + (size_t)rr * NGATE;
                float gi = acc[0][cell] + Gr[jloc];
                float gf = acc[1][cell] + Gr[8 + jloc];
                float gg = acc[2][cell] + Gr[16 + jloc];
                float go = acc[3][cell] + Gr[24 + jloc];
                int j = jblk * 8 + jloc;
                float cc = creg[cell];
                cc = sigm(gf) * cc + sigm(gi) * tanhf(gg);
                float hh = sigm(go) * tanhf(cc);
                creg[cell] = cc;
                Awr[rr * HE + j] = hh;
                Hout[((size_t)time * NB + rr) * HD + dir * HE + j] = hh;
            }
        }
        sync_grid();
    }
}

// ---------------- persistent decoder ----------------
__global__ __launch_bounds__(256) void dec_persistent(
    const float* __restrict__ whh, const float* __restrict__ bias,
    const float* __restrict__ wih,
    const float* __restrict__ out_w, const float* __restrict__ out_b,
    const int* __restrict__ tag_ids, float* __restrict__ prob_out)
{
    int tid = threadIdx.x, bid = blockIdx.x;
    int lane = tid & 31, w = tid >> 5;
    int r0 = (w << 4) + (lane >> 2);
    int jj2 = (lane & 3) * 2;
    int j0 = bid * 8;

    // hsum[0] = h0(=0) + enc_0
#pragma unroll
    for (int p = 0; p < 4; p++) {
        int idx = (bid * 4 + p) * 256 + tid;
        g_hsum[0][idx] = g_ENC[idx];      // enc[t=0] occupies the first NB*HD block
    }
    if (bid == 0 && tid < NB) g_previdx[tid] = -1;
    if (bid == 0 && tid == 0) g_loss = 0.f;

    // register cell state: cell0 = enc[0][n][HE + (j & 511)]
    float creg[4];
#pragma unroll
    for (int cell = 0; cell < 4; cell++) {
        int rr = r0 + (cell >> 1) * 8;
        int j = j0 + jj2 + (cell & 1);
        creg[cell] = g_ENC[(size_t)rr * HD + HE + (j & (HE - 1))];
    }

    // preload bias
    float biasReg[4][2];
#pragma unroll
    for (int g = 0; g < 4; g++) {
        biasReg[g][0] = bias[g * HD + j0 + jj2];
        biasReg[g][1] = bias[g * HD + j0 + jj2 + 1];
    }
    sync_grid();

    __shared__ float sA[128 * 36];
    __shared__ float sB[32 * 36];
    __shared__ float sh[HD];
    __shared__ float red[256];
    __shared__ float logitsS[TT];
    __shared__ float sLogZ;
    __shared__ int sArg;

    for (int t = 0; t < LSEQ; t++) {
        const float* Ain = g_hsum[t & 1];
        float* Anext = g_hsum[(t + 1) & 1];
        float acc[4][4];
#pragma unroll
        for (int a = 0; a < 4; a++)
#pragma unroll
            for (int c = 0; c < 4; c++) acc[a][c] = 0.f;

        for (int k0 = 0; k0 < HD; k0 += 32) {
#pragma unroll
            for (int p = 0; p < 16; p++) {
                int idx = tid + p * 256;
                int r = idx >> 5, c = idx & 31;
                sA[r * 36 + c] = Ain[(size_t)r * HD + k0 + c];
            }
#pragma unroll
            for (int p = 0; p < 4; p++) {
                int idx = tid + p * 256;
                int r = idx >> 5, c = idx & 31;
                int nat = (r >> 3) * HD + j0 + (r & 7);
                sB[r * 36 + c] = whh[(size_t)nat * HD + k0 + c];
            }
            __syncthreads();
#pragma unroll
            for (int kk = 0; kk < 32; kk += 8) {
                int ac = kk + (lane & 3);
                unsigned ah[4], al[4];
                tf32_split(sA[r0 * 36 + ac],           ah[0], al[0]);
                tf32_split(sA[(r0 + 8) * 36 + ac],     ah[1], al[1]);
                tf32_split(sA[r0 * 36 + ac + 4],       ah[2], al[2]);
                tf32_split(sA[(r0 + 8) * 36 + ac + 4], ah[3], al[3]);
#pragma unroll
                for (int nf = 0; nf < 4; nf++) {
                    int br = nf * 8 + (lane >> 2);
                    int bc = kk + (lane & 3);
                    unsigned bh0, bl0, bh1, bl1;
                    tf32_split(sB[br * 36 + bc],     bh0, bl0);
                    tf32_split(sB[br * 36 + bc + 4], bh1, bl1);
                    mma8(acc[nf], al[0], al[1], al[2], al[3], bh0, bh1);
                    mma8(acc[nf], ah[0], ah[1], ah[2], ah[3], bl0, bl1);
                    mma8(acc[nf], ah[0], ah[1], ah[2], ah[3], bh0, bh1);
                }
            }
            __syncthreads();
        }
        // pointwise: write raw h (for logits) + h+enc_{t+1} (next GEMM A) into ping buffer
        {
            int pv0 = g_previdx[r0];
            int pv1 = g_previdx[r0 + 8];
#pragma unroll
            for (int cell = 0; cell < 4; cell++) {
                int rr = r0 + (cell >> 1) * 8;
                int pv = (cell >> 1) ? pv1 : pv0;
                int s = cell & 1;
                int jloc = jj2 + s;
                int j = j0 + jloc;
                float gi = acc[0][cell] + biasReg[0][s];
                float gf = acc[1][cell] + biasReg[1][s];
                float gg = acc[2][cell] + biasReg[2][s];
                float go = acc[3][cell] + biasReg[3][s];
                if (pv >= 0) {
                    gi += wih[(0 * HD + j) * TT + pv];
                    gf += wih[(1 * HD + j) * TT + pv];
                    gg += wih[(2 * HD + j) * TT + pv];
                    go += wih[(3 * HD + j) * TT + pv];
                }
                float cc = creg[cell];
                cc = sigm(gf) * cc + sigm(gi) * tanhf(gg);
                float hh = sigm(go) * tanhf(cc);
                creg[cell] = cc;
                g_hraw[rr * HD + j] = hh;
                if (t + 1 < LSEQ)
                    Anext[(size_t)rr * HD + j] = hh + g_ENC[((size_t)(t + 1) * NB + rr) * HD + j];
            }
        }
        sync_grid();
        // logits + softmax + argmax + loss: CTA bid handles batch row bid
        {
            int n = bid;
#pragma unroll
            for (int p = 0; p < 4; p++) {
                int j = tid + p * 256;
                sh[j] = g_hraw[n * HD + j];
            }
            __syncthreads();
            {
                int lj = tid & (TT - 1), half = tid >> 7;
                const float* wr = out_w + (size_t)lj * HD + half * 512;
                const float* hr = sh + half * 512;
                float s = 0.f;
#pragma unroll 8
                for (int k = 0; k < 512; k++) s += hr[k] * wr[k];
                red[tid] = s;
            }
            __syncthreads();
            if (tid < TT) logitsS[tid] = red[tid] + red[tid + TT] + out_b[tid];
            __syncthreads();
            if (tid < 32) {
                float bv = -1e30f; int bi = 0;
#pragma unroll
                for (int p = 0; p < 4; p++) {
                    int k = tid + p * 32;
                    float v = logitsS[k];
                    if (v > bv) { bv = v; bi = k; }
                }
#pragma unroll
                for (int off = 16; off; off >>= 1) {
                    float ov = __shfl_down_sync(0xffffffffu, bv, off);
                    int   oi = __shfl_down_sync(0xffffffffu, bi, off);
                    if (ov > bv || (ov == bv && oi < bi)) { bv = ov; bi = oi; }
                }
                bv = __shfl_sync(0xffffffffu, bv, 0);
                bi = __shfl_sync(0xffffffffu, bi, 0);
                float s = 0.f;
#pragma unroll
                for (int p = 0; p < 4; p++) s += expf(logitsS[tid + p * 32] - bv);
#pragma unroll
                for (int off = 16; off; off >>= 1) s += __shfl_down_sync(0xffffffffu, s, off);
                if (tid == 0) { sLogZ = bv + logf(s); sArg = bi; }
            }
            __syncthreads();
            if (tid < TT)
                prob_out[(size_t)n * (LSEQ * TT) + t * TT + tid] = expf(logitsS[tid] - sLogZ);
            if (tid == 0) {
                g_previdx[n] = sArg;
                int tag = tag_ids[n * LSEQ + t];
                atomicAdd(&g_loss, -(logitsS[tag] - sLogZ) * (1.0f / NB));
            }
        }
        sync_grid();
    }
    if (bid == 0 && tid == 0) prob_out[(size_t)NB * LSEQ * TT] = g_loss;
}

// ---------------- launch: 5 graph nodes ----------------
extern "C" void kernel_launch(void* const* d_in, const int* in_sizes, int n_in,
                              void* d_out, int out_size)
{
    const int*   input_ids = (const int*)d_in[0];
    const int*   tag_ids   = (const int*)d_in[1];
    const float* embed     = (const float*)d_in[2];
    const float* e0_wih    = (const float*)d_in[3];
    const float* e0_whh    = (const float*)d_in[4];
    const float* e0_b      = (const float*)d_in[5];
    const float* e1_wih    = (const float*)d_in[6];
    const float* e1_whh    = (const float*)d_in[7];
    const float* e1_b      = (const float*)d_in[8];
    const float* dec_wih   = (const float*)d_in[9];
    const float* dec_whh   = (const float*)d_in[10];
    const float* dec_b     = (const float*)d_in[11];
    const float* out_w     = (const float*)d_in[12];
    const float* out_b     = (const float*)d_in[13];
    float* out = (float*)d_out;
    (void)in_sizes; (void)n_in; (void)out_size;

    dim3 ggrid(NGATE / 128, (LSEQ * NB) / 128);   // 32 x 160

    inproj_gemm<1, EMB><<<ggrid, 256>>>(e0_wih, e0_b, embed, input_ids);
    enc_layer_persistent<<<GRID, 256>>>(e0_whh, 0);
    inproj_gemm<0, HD><<<ggrid, 256>>>(e1_wih, e1_b, embed, input_ids);
    enc_layer_persistent<<<GRID, 256>>>(e1_whh, 1);
    dec_persistent<<<GRID, 256>>>(dec_whh, dec_b, dec_wih, out_w, out_b, tag_ids, out);
}